// round 16
// baseline (speedup 1.0000x reference)
#include <cuda_runtime.h>
#include <cuda_fp16.h>
#include <cstdint>

#define MTOK 8192
#define HID  2048
#define DEX  4096
#define RK   64
#define K1P  HID       // 2048  GEMM1 K (plain fp16 both sides)
#define K2P  DEX       // 4096  GEMM2 K (plain fp16 both sides)
#define KRE  (2*RK)    // 128   LoRA tail K (split pairs)
#define SPLITK 4
// scaling: A-side stored = 16*true, B-side = 64*true, GEMM raw = 1024*true
#define INV_GEMM (1.0f/1024.0f)

// ---------------- scratch (device globals) ----------------------------------
__device__ __align__(16) __half g_Xe  [(size_t)MTOK * K1P];
__device__ __align__(16) __half g_Wgue[(size_t)2*DEX * K1P];
__device__ __align__(16) __half g_Ague[(size_t)RK * K1P];
__device__ __align__(16) __half g_Bgue[(size_t)2*DEX * KRE];
__device__ __align__(16) __half g_Wde [(size_t)HID * K2P];
__device__ __align__(16) __half g_Ade [(size_t)RK * K2P];
__device__ __align__(16) __half g_Bde [(size_t)HID * KRE];
__device__ __align__(16) float  g_Pk  [(size_t)SPLITK * MTOK * RK];
__device__ __align__(16) __half g_T1e [(size_t)MTOK * KRE];
__device__ __align__(16) __half g_T2e [(size_t)MTOK * KRE];
__device__ __align__(16) __half g_He  [(size_t)MTOK * K2P];

// ---------------- batched conversions ----------------------------------------
// dup=0: plain fp16 (8 in -> 8 out). dup=1: B-dup pairs (8 in -> 16 out).
struct CvtSeg { const float* in; __half* out; size_t n8; float scale; int dup; };
struct CvtTab2 { CvtSeg s[2]; size_t cum8[3]; };
struct CvtTab5 { CvtSeg s[5]; size_t cum8[6]; };

__device__ __forceinline__ void cvt_one(const CvtSeg& sg, size_t j) {
    const float4* p = reinterpret_cast<const float4*>(sg.in) + j * 2;
    float4 v0 = p[0], v1 = p[1];
    float x[8] = {v0.x, v0.y, v0.z, v0.w, v1.x, v1.y, v1.z, v1.w};
    if (!sg.dup) {
        __half ob[8];
#pragma unroll
        for (int k = 0; k < 8; k++) ob[k] = __float2half_rn(x[k] * sg.scale);
        *reinterpret_cast<uint4*>(sg.out + j * 8) =
            *reinterpret_cast<const uint4*>(ob);
    } else {
        __half ob[16];
#pragma unroll
        for (int k = 0; k < 8; k++) {
            __half hi = __float2half_rn(x[k] * sg.scale);
            ob[2*k] = hi; ob[2*k+1] = hi;
        }
        uint4* o = reinterpret_cast<uint4*>(sg.out + j * 16);
        const uint4* s = reinterpret_cast<const uint4*>(ob);
        o[0] = s[0]; o[1] = s[1];
    }
}

__global__ void cvt_small(CvtTab2 tab) {
    size_t i = (size_t)blockIdx.x * blockDim.x + threadIdx.x;
    if (i >= tab.cum8[2]) return;
    int sidx = (i >= tab.cum8[1]) ? 1 : 0;
    cvt_one(tab.s[sidx], i - tab.cum8[sidx]);
}

__global__ void cvt_big(CvtTab5 tab) {
    size_t i = (size_t)blockIdx.x * blockDim.x + threadIdx.x;
    if (i >= tab.cum8[5]) return;
    int sidx = 0;
#pragma unroll
    for (int k = 1; k < 5; k++) sidx += (i >= tab.cum8[k]) ? 1 : 0;
    cvt_one(tab.s[sidx], i - tab.cum8[sidx]);
}

// ---------------- splitK reduce + scale + A-side fp16 pair (x4 vec) ---------
__global__ void reduce_expand4(const float* __restrict__ P,
                               __half* __restrict__ out) {
    size_t q = (size_t)blockIdx.x * blockDim.x + threadIdx.x;
    if (q >= (size_t)MTOK * RK / 4) return;
    const size_t S = (size_t)MTOK * RK;
    size_t base = q * 4;
    float4 a = *reinterpret_cast<const float4*>(P + base);
    float4 b = *reinterpret_cast<const float4*>(P + S + base);
    float4 c = *reinterpret_cast<const float4*>(P + 2*S + base);
    float4 d = *reinterpret_cast<const float4*>(P + 3*S + base);
    float s[4] = {(a.x+b.x+c.x+d.x) * (1.0f/256.0f),
                  (a.y+b.y+c.y+d.y) * (1.0f/256.0f),
                  (a.z+b.z+c.z+d.z) * (1.0f/256.0f),
                  (a.w+b.w+c.w+d.w) * (1.0f/256.0f)};
    __half ob[8];
#pragma unroll
    for (int k = 0; k < 4; k++) {
        __half hi = __float2half_rn(s[k]);
        ob[2*k]   = hi;
        ob[2*k+1] = __float2half_rn(s[k] - __half2float(hi));
    }
    *reinterpret_cast<uint4*>(out + base * 2) =
        *reinterpret_cast<const uint4*>(ob);
}

// ============================================================================
// SQ kernel: CTA 128x128, 4 warps (2x2) of 64x64, 128 threads, 2 CTAs/SM,
// double-buffered fragments.  MODE 0: C fp32 (descaled) + LoRA tail.
// MODE 1: fused SwiGLU -> He plain fp16 (x16), gate/up interleaved B rows.
// ============================================================================
#define BMS 128
#define BNS 128
#define STG_S 3
#define NTH_S 128
#define TILE_S (128 * 64 * 2)                  // 16 KB
#define SMEM_S (2 * STG_S * TILE_S)            // 96 KB

template<int MODE>
__device__ __forceinline__ void load_tiles_s(uint32_t smem_u32, int stage,
                                             const __half* gA,
                                             const __half* gB,
                                             int m0, int n0, int Ks,
                                             int kt, int tid) {
#pragma unroll
    for (int i = 0; i < 8; i++) {
        int c = tid + i * NTH_S;        // 0..1023 16B chunks per operand
        int row = c >> 3;
        int col = c & 7;
        uint32_t sw = (uint32_t)(col ^ (row & 7)) << 4;
        uint32_t da = smem_u32 + (uint32_t)stage * TILE_S + row * 128 + sw;
        const void* sa = (const void*)(gA + (size_t)(m0 + row) * Ks
                                          + (size_t)kt * 64 + col * 8);
        asm volatile("cp.async.cg.shared.global [%0], [%1], 16;"
                     :: "r"(da), "l"(sa));
        int brow;
        if (MODE == 1) {                // gate/up interleave; n0 = d-offset
            brow = (row & 1) ? (DEX + n0 + (row >> 1)) : (n0 + (row >> 1));
        } else {
            brow = n0 + row;
        }
        uint32_t db = smem_u32 + (uint32_t)(STG_S + stage) * TILE_S
                               + row * 128 + sw;
        const void* sb = (const void*)(gB + (size_t)brow * Ks
                                          + (size_t)kt * 64 + col * 8);
        asm volatile("cp.async.cg.shared.global [%0], [%1], 16;"
                     :: "r"(db), "l"(sb));
    }
}

template<int MODE>
__global__ __launch_bounds__(NTH_S, 2) void gemm_sq(
    const __half* __restrict__ A,  const __half* __restrict__ B,
    const __half* __restrict__ A2, const __half* __restrict__ B2,
    void* __restrict__ Cout, int N, int K, int Kt) {
    extern __shared__ char smem[];
    const uint32_t smem_u32 = (uint32_t)__cvta_generic_to_shared(smem);
    const int tid  = threadIdx.x;
    const int warp = tid >> 5, lane = tid & 31;
    const int wm = warp >> 1, wn = warp & 1;   // 2x2 warps of 64x64
    const int gid = lane >> 2, tig = lane & 3;

    // grouped CTA swizzle (8 y-tiles per x step) for L2 reuse of B panels
    int bx = blockIdx.x, by = blockIdx.y;
    if (gridDim.x > 1) {
        const int GRP = 8;
        int lin = by * gridDim.x + bx;
        int per = gridDim.x * GRP;
        int g   = lin / per, rem = lin % per;
        int gy  = g * GRP;
        int h   = gridDim.y - gy; if (h > GRP) h = GRP;
        by = gy + rem % h;
        bx = rem / h;
    }
    const int m0 = by * BMS;
    const int n0 = bx * ((MODE == 1) ? 64 : BNS);

    float acc[4][8][4];
#pragma unroll
    for (int a = 0; a < 4; a++)
#pragma unroll
        for (int b = 0; b < 8; b++)
#pragma unroll
            for (int c = 0; c < 4; c++) acc[a][b][c] = 0.0f;

    const int a_row_in = (lane & 15);
    const int a_ch_in  = (lane >> 4);
    const int b_row_in = ((lane >> 4) << 3) + (lane & 7);
    const int b_ch_in  = ((lane >> 3) & 1);

    for (int seg = 0; seg < 2; seg++) {
        const __half* gA = seg ? A2 : A;
        const __half* gB = seg ? B2 : B;
        const int Ks = seg ? Kt : K;
        if (Ks == 0) break;
        const int ktiles = Ks / 64;

        for (int p = 0; p < STG_S - 1; p++) {
            if (p < ktiles)
                load_tiles_s<MODE>(smem_u32, p, gA, gB, m0, n0, Ks, p, tid);
            asm volatile("cp.async.commit_group;");
        }

        for (int kt = 0; kt < ktiles; kt++) {
            asm volatile("cp.async.wait_group %0;" :: "n"(STG_S - 2));
            __syncthreads();

            const int st = kt % STG_S;
            const uint32_t sA = smem_u32 + (uint32_t)st * TILE_S;
            const uint32_t sB = smem_u32 + (uint32_t)(STG_S + st) * TILE_S;

            uint32_t ra[2][4][4], rb[2][8][2];
            auto frags = [&](int kk, int buf) {
#pragma unroll
                for (int mi = 0; mi < 4; mi++) {
                    int row = wm * 64 + mi * 16 + a_row_in;
                    int ch  = (kk >> 3) + a_ch_in;
                    uint32_t ad = sA + row * 128 + ((uint32_t)(ch ^ (row & 7)) << 4);
                    asm volatile(
                        "ldmatrix.sync.aligned.m8n8.x4.shared.b16 {%0,%1,%2,%3}, [%4];"
                        : "=r"(ra[buf][mi][0]), "=r"(ra[buf][mi][1]),
                          "=r"(ra[buf][mi][2]), "=r"(ra[buf][mi][3])
                        : "r"(ad));
                }
#pragma unroll
                for (int p = 0; p < 4; p++) {
                    int row = wn * 64 + p * 16 + b_row_in;
                    int ch  = (kk >> 3) + b_ch_in;
                    uint32_t bd = sB + row * 128 + ((uint32_t)(ch ^ (row & 7)) << 4);
                    asm volatile(
                        "ldmatrix.sync.aligned.m8n8.x4.shared.b16 {%0,%1,%2,%3}, [%4];"
                        : "=r"(rb[buf][2*p][0]), "=r"(rb[buf][2*p][1]),
                          "=r"(rb[buf][2*p+1][0]), "=r"(rb[buf][2*p+1][1])
                        : "r"(bd));
                }
            };
            auto mmas = [&](int buf) {
#pragma unroll
                for (int mi = 0; mi < 4; mi++)
#pragma unroll
                    for (int ni = 0; ni < 8; ni++)
                        asm volatile(
                            "mma.sync.aligned.m16n8k16.row.col.f32.f16.f16.f32 "
                            "{%0,%1,%2,%3}, {%4,%5,%6,%7}, {%8,%9}, {%0,%1,%2,%3};"
                            : "+f"(acc[mi][ni][0]), "+f"(acc[mi][ni][1]),
                              "+f"(acc[mi][ni][2]), "+f"(acc[mi][ni][3])
                            : "r"(ra[buf][mi][0]), "r"(ra[buf][mi][1]),
                              "r"(ra[buf][mi][2]), "r"(ra[buf][mi][3]),
                              "r"(rb[buf][ni][0]), "r"(rb[buf][ni][1]));
            };

            frags(0, 0);
            frags(16, 1);
            mmas(0);
            int nk = kt + STG_S - 1;
            if (nk < ktiles)
                load_tiles_s<MODE>(smem_u32, nk % STG_S, gA, gB, m0, n0, Ks,
                                   nk, tid);
            asm volatile("cp.async.commit_group;");
            frags(32, 0);
            mmas(1);
            frags(48, 1);
            mmas(0);
            mmas(1);
        }
        asm volatile("cp.async.wait_group 0;");
        __syncthreads();
    }

    if (MODE == 0) {
        float* C = (float*)Cout;
#pragma unroll
        for (int mi = 0; mi < 4; mi++) {
            int r0 = m0 + wm * 64 + mi * 16 + gid;
#pragma unroll
            for (int ni = 0; ni < 8; ni++) {
                int c0 = n0 + wn * 64 + ni * 8 + tig * 2;
                float2 v0 = make_float2(acc[mi][ni][0] * INV_GEMM,
                                        acc[mi][ni][1] * INV_GEMM);
                float2 v1 = make_float2(acc[mi][ni][2] * INV_GEMM,
                                        acc[mi][ni][3] * INV_GEMM);
                *reinterpret_cast<float2*>(C + (size_t)r0 * N + c0) = v0;
                *reinterpret_cast<float2*>(C + (size_t)(r0 + 8) * N + c0) = v1;
            }
        }
    } else {
        // MODE 1: acc pair (c0,c1) = (gate,up) raw; local d = wn*32+ni*4+tig
        float* hs = reinterpret_cast<float*>(smem);   // [128][68] padded
#pragma unroll
        for (int mi = 0; mi < 4; mi++) {
            int rl = wm * 64 + mi * 16 + gid;
#pragma unroll
            for (int ni = 0; ni < 8; ni++) {
                int dl = wn * 32 + ni * 4 + tig;      // 0..63
                float g0 = acc[mi][ni][0] * INV_GEMM, u0 = acc[mi][ni][1] * INV_GEMM;
                hs[rl * 68 + dl]       = u0 * g0 / (1.0f + __expf(-g0));
                float g1 = acc[mi][ni][2] * INV_GEMM, u1 = acc[mi][ni][3] * INV_GEMM;
                hs[(rl + 8) * 68 + dl] = u1 * g1 / (1.0f + __expf(-g1));
            }
        }
        __syncthreads();
        __half* He = (__half*)Cout;
#pragma unroll
        for (int it = 0; it < 8; it++) {
            int rl  = it * 16 + (tid >> 3);
            int blk = tid & 7;
            float4 v0 = *reinterpret_cast<float4*>(&hs[rl * 68 + blk * 8]);
            float4 v1 = *reinterpret_cast<float4*>(&hs[rl * 68 + blk * 8 + 4]);
            float x[8] = {v0.x, v0.y, v0.z, v0.w, v1.x, v1.y, v1.z, v1.w};
            __half ob[8];
#pragma unroll
            for (int k = 0; k < 8; k++)
                ob[k] = __float2half_rn(x[k] * 16.0f);    // A-side scale
            *reinterpret_cast<uint4*>(
                He + (size_t)(m0 + rl) * K2P + (n0 + blk * 8)) =
                *reinterpret_cast<const uint4*>(ob);
        }
    }
}

// ============================================================================
// LoRA splitK kernel: CTA 128x64, 4 warps (2x2) of 64x32, 128 threads.
// B tile only 64 rows (8 KB/stage). Raw partials to Pk[split].
// ============================================================================
#define BM_L 128
#define STG_L 3
#define NTH_L 128
#define ATILE_L (128 * 64 * 2)                 // 16 KB
#define BTILE_L (64 * 64 * 2)                  // 8 KB
#define SMEM_L (STG_L * (ATILE_L + BTILE_L))   // 72 KB -> 2 CTAs/SM

__device__ __forceinline__ void load_tiles_l(uint32_t smem_u32, int stage,
                                             const __half* gA,
                                             const __half* gB,
                                             int m0, int Ks, int kt, int tid) {
#pragma unroll
    for (int i = 0; i < 12; i++) {      // 1024 A + 512 B chunks, 128 thr
        int c = tid + i * NTH_L;
        if (c < 1024) {
            int row = c >> 3, col = c & 7;
            uint32_t sw = (uint32_t)(col ^ (row & 7)) << 4;
            uint32_t da = smem_u32 + (uint32_t)stage * ATILE_L + row * 128 + sw;
            const void* sa = (const void*)(gA + (size_t)(m0 + row) * Ks
                                              + (size_t)kt * 64 + col * 8);
            asm volatile("cp.async.cg.shared.global [%0], [%1], 16;"
                         :: "r"(da), "l"(sa));
        } else {
            int b = c - 1024;
            int row = b >> 3, col = b & 7;   // row 0..63
            uint32_t sw = (uint32_t)(col ^ (row & 7)) << 4;
            uint32_t db = smem_u32 + (uint32_t)(STG_L * ATILE_L)
                                   + (uint32_t)stage * BTILE_L + row * 128 + sw;
            const void* sb = (const void*)(gB + (size_t)row * Ks
                                              + (size_t)kt * 64 + col * 8);
            asm volatile("cp.async.cg.shared.global [%0], [%1], 16;"
                         :: "r"(db), "l"(sb));
        }
    }
}

__global__ __launch_bounds__(NTH_L, 2) void gemm_lora(
    const __half* __restrict__ A, const __half* __restrict__ B,
    float* __restrict__ Cout, int K) {
    extern __shared__ char smem[];
    const uint32_t smem_u32 = (uint32_t)__cvta_generic_to_shared(smem);
    const int tid  = threadIdx.x;
    const int warp = tid >> 5, lane = tid & 31;
    const int wm = warp >> 1, wn = warp & 1;   // 2x2 warps of 64x32
    const int gid = lane >> 2, tig = lane & 3;
    const int m0 = blockIdx.y * BM_L;

    float acc[4][4][4];
#pragma unroll
    for (int a = 0; a < 4; a++)
#pragma unroll
        for (int b = 0; b < 4; b++)
#pragma unroll
            for (int c = 0; c < 4; c++) acc[a][b][c] = 0.0f;

    const int a_row_in = (lane & 15);
    const int a_ch_in  = (lane >> 4);
    const int b_row_in = ((lane >> 4) << 3) + (lane & 7);
    const int b_ch_in  = ((lane >> 3) & 1);

    const int cps  = (K / 64) / SPLITK;
    const int koff = blockIdx.z * cps;

    for (int p = 0; p < STG_L - 1; p++) {
        if (p < cps)
            load_tiles_l(smem_u32, p, A, B, m0, K, koff + p, tid);
        asm volatile("cp.async.commit_group;");
    }
    for (int kt = 0; kt < cps; kt++) {
        asm volatile("cp.async.wait_group %0;" :: "n"(STG_L - 2));
        __syncthreads();
        int nk = kt + STG_L - 1;
        if (nk < cps)
            load_tiles_l(smem_u32, nk % STG_L, A, B, m0, K, koff + nk, tid);
        asm volatile("cp.async.commit_group;");

        const int st = kt % STG_L;
        const uint32_t sA = smem_u32 + (uint32_t)st * ATILE_L;
        const uint32_t sB = smem_u32 + (uint32_t)(STG_L * ATILE_L)
                                     + (uint32_t)st * BTILE_L;
#pragma unroll
        for (int kk = 0; kk < 64; kk += 16) {
            uint32_t ra[4][4], rb[4][2];
#pragma unroll
            for (int mi = 0; mi < 4; mi++) {
                int row = wm * 64 + mi * 16 + a_row_in;
                int ch  = (kk >> 3) + a_ch_in;
                uint32_t ad = sA + row * 128 + ((uint32_t)(ch ^ (row & 7)) << 4);
                asm volatile(
                    "ldmatrix.sync.aligned.m8n8.x4.shared.b16 {%0,%1,%2,%3}, [%4];"
                    : "=r"(ra[mi][0]), "=r"(ra[mi][1]),
                      "=r"(ra[mi][2]), "=r"(ra[mi][3])
                    : "r"(ad));
            }
#pragma unroll
            for (int p = 0; p < 2; p++) {
                int row = wn * 32 + p * 16 + b_row_in;   // 0..63
                int ch  = (kk >> 3) + b_ch_in;
                uint32_t bd = sB + row * 128 + ((uint32_t)(ch ^ (row & 7)) << 4);
                asm volatile(
                    "ldmatrix.sync.aligned.m8n8.x4.shared.b16 {%0,%1,%2,%3}, [%4];"
                    : "=r"(rb[2*p][0]), "=r"(rb[2*p][1]),
                      "=r"(rb[2*p+1][0]), "=r"(rb[2*p+1][1])
                    : "r"(bd));
            }
#pragma unroll
            for (int mi = 0; mi < 4; mi++)
#pragma unroll
                for (int ni = 0; ni < 4; ni++)
                    asm volatile(
                        "mma.sync.aligned.m16n8k16.row.col.f32.f16.f16.f32 "
                        "{%0,%1,%2,%3}, {%4,%5,%6,%7}, {%8,%9}, {%0,%1,%2,%3};"
                        : "+f"(acc[mi][ni][0]), "+f"(acc[mi][ni][1]),
                          "+f"(acc[mi][ni][2]), "+f"(acc[mi][ni][3])
                        : "r"(ra[mi][0]), "r"(ra[mi][1]),
                          "r"(ra[mi][2]), "r"(ra[mi][3]),
                          "r"(rb[ni][0]), "r"(rb[ni][1]));
        }
    }
    asm volatile("cp.async.wait_group 0;");
    __syncthreads();

    float* C = Cout + (size_t)blockIdx.z * MTOK * RK;
#pragma unroll
    for (int mi = 0; mi < 4; mi++) {
        int r0 = m0 + wm * 64 + mi * 16 + gid;
#pragma unroll
        for (int ni = 0; ni < 4; ni++) {
            int c0 = wn * 32 + ni * 8 + tig * 2;   // 0..63 always valid
            float2 v0 = make_float2(acc[mi][ni][0], acc[mi][ni][1]);
            float2 v1 = make_float2(acc[mi][ni][2], acc[mi][ni][3]);
            *reinterpret_cast<float2*>(C + (size_t)r0 * RK + c0) = v0;
            *reinterpret_cast<float2*>(C + (size_t)(r0 + 8) * RK + c0) = v1;
        }
    }
}

// ---------------- launcher ---------------------------------------------------
extern "C" void kernel_launch(void* const* d_in, const int* in_sizes, int n_in,
                              void* d_out, int out_size) {
    const float* X   = (const float*)d_in[0];
    const float* Wgu = (const float*)d_in[1];
    const float* Agu = (const float*)d_in[2];
    const float* Bgu = (const float*)d_in[3];
    const float* Wd  = (const float*)d_in[4];
    const float* Ad  = (const float*)d_in[5];
    const float* Bd  = (const float*)d_in[6];
    float* out = (float*)d_out;

    __half *Xe, *Wgue, *Ague, *Bgue, *Wde, *Ade, *Bde, *T1e, *T2e, *He;
    float *Pk;
    cudaGetSymbolAddress((void**)&Xe,   g_Xe);
    cudaGetSymbolAddress((void**)&Wgue, g_Wgue);
    cudaGetSymbolAddress((void**)&Ague, g_Ague);
    cudaGetSymbolAddress((void**)&Bgue, g_Bgue);
    cudaGetSymbolAddress((void**)&Wde,  g_Wde);
    cudaGetSymbolAddress((void**)&Ade,  g_Ade);
    cudaGetSymbolAddress((void**)&Bde,  g_Bde);
    cudaGetSymbolAddress((void**)&Pk,   g_Pk);
    cudaGetSymbolAddress((void**)&T1e,  g_T1e);
    cudaGetSymbolAddress((void**)&T2e,  g_T2e);
    cudaGetSymbolAddress((void**)&He,   g_He);

    cudaFuncSetAttribute(gemm_sq<0>,
                         cudaFuncAttributeMaxDynamicSharedMemorySize, SMEM_S);
    cudaFuncSetAttribute(gemm_sq<1>,
                         cudaFuncAttributeMaxDynamicSharedMemorySize, SMEM_S);
    cudaFuncSetAttribute(gemm_lora,
                         cudaFuncAttributeMaxDynamicSharedMemorySize, SMEM_L);

    // one-time side stream + events (created outside capture on first call;
    // no device memory is allocated by streams/events)
    static cudaStream_t s1 = nullptr;
    static cudaEvent_t evFork = nullptr, evJoin = nullptr;
    if (s1 == nullptr) {
        cudaStreamCreateWithFlags(&s1, cudaStreamNonBlocking);
        cudaEventCreateWithFlags(&evFork, cudaEventDisableTiming);
        cudaEventCreateWithFlags(&evJoin, cudaEventDisableTiming);
    }

    const int T = 256;

    // ---- stream0: convert only what lora1 needs (X, Agu) ----
    CvtTab2 ts;
    ts.s[0] = { X,   Xe,   (size_t)MTOK * HID / 8, 16.0f, 0 };
    ts.s[1] = { Agu, Ague, (size_t)RK * HID / 8,   64.0f, 0 };
    ts.cum8[0] = 0;
    ts.cum8[1] = ts.s[0].n8;
    ts.cum8[2] = ts.cum8[1] + ts.s[1].n8;
    cvt_small<<<(unsigned)((ts.cum8[2] + T - 1) / T), T>>>(ts);

    // ---- fork: stream1 converts the remaining 5 operands concurrently ----
    cudaEventRecord(evFork, 0);
    cudaStreamWaitEvent(s1, evFork, 0);
    CvtTab5 tbg;
    tbg.s[0] = { Wgu, Wgue, (size_t)2 * DEX * HID / 8, 64.0f, 0 };
    tbg.s[1] = { Wd,  Wde,  (size_t)HID * DEX / 8,     64.0f, 0 };
    tbg.s[2] = { Ad,  Ade,  (size_t)RK * DEX / 8,      64.0f, 0 };
    tbg.s[3] = { Bgu, Bgue, (size_t)2 * DEX * RK / 8,  64.0f, 1 };
    tbg.s[4] = { Bd,  Bde,  (size_t)HID * RK / 8,      64.0f, 1 };
    tbg.cum8[0] = 0;
    for (int k = 0; k < 5; k++) tbg.cum8[k+1] = tbg.cum8[k] + tbg.s[k].n8;
    cvt_big<<<(unsigned)((tbg.cum8[5] + T - 1) / T), T, 0, s1>>>(tbg);
    cudaEventRecord(evJoin, s1);

    const unsigned gr4 = (unsigned)(((size_t)MTOK * RK / 4 + T - 1) / T);

    // ---- stream0 (overlapped with cvt_big): T1 lora chain ----
    gemm_lora<<<dim3(1, MTOK/BM_L, SPLITK), NTH_L, SMEM_L>>>(Xe, Ague, Pk, K1P);
    reduce_expand4<<<gr4, T>>>(Pk, T1e);

    // ---- join: gemm1 needs Wgue/Bgue from stream1 ----
    cudaStreamWaitEvent(0, evJoin, 0);

    // He = 16*swiglu(X@Wgu^T + 0.25*T1@Bgu^T), plain fp16 (square 64x64 warps)
    gemm_sq<1><<<dim3(DEX/64, MTOK/BMS), NTH_S, SMEM_S>>>(
        Xe, Wgue, T1e, Bgue, He, 2*DEX, K1P, KRE);

    // T2 raw = 1024*(H @ Ad^T), splitK x4 -> reduce -> T2e
    gemm_lora<<<dim3(1, MTOK/BM_L, SPLITK), NTH_L, SMEM_L>>>(He, Ade, Pk, K2P);
    reduce_expand4<<<gr4, T>>>(Pk, T2e);

    // out = H@Wd^T + 0.25*T2@Bd^T (square 64x64 warps)
    gemm_sq<0><<<dim3(HID/BNS, MTOK/BMS), NTH_S, SMEM_S>>>(
        He, Wde, T2e, Bde, out, HID, K2P, KRE);
}